// round 9
// baseline (speedup 1.0000x reference)
#include <cuda_runtime.h>
#include <cstdint>

// ContextEmbedding: B=256, S=512, D=256. token ids in [0,76); special=[68,76);
// CLS=68, CONTEXT=69. Output f32 [B*S,256] = 134 MB.
//
// R8: bypass the per-thread STG path (plateaued at ~5.1 TB/s across R2-R7)
// by building output rows in SMEM and draining them with TMA bulk stores
// (cp.async.bulk.global.shared::cta), whose chip throughput is the LTS cap
// (path-independent, ~2x the STG plateau). CTA owns 256 rows, built in 4
// chunks of 64 rows (64 KB) in a double-buffered dynamic SMEM region;
// one elected thread issues one 64 KB bulk store per chunk.

#define D_MODEL        256
#define NUM_CONTEXT    16
#define SPECIAL_OFFSET 68
#define NUM_SPECIAL    8
#define LN_EPS         1e-5f
#define FULL           0xffffffffu

#define ROWS_PER_CTA   256
#define CHUNK_ROWS     64
#define NUM_CHUNKS     (ROWS_PER_CTA / CHUNK_ROWS)     // 4
#define ROW_FLOATS     D_MODEL
#define BUF_FLOATS     (CHUNK_ROWS * ROW_FLOATS)       // 16384 floats = 64 KB
#define BUF_BYTES      (BUF_FLOATS * 4)                // 65536
#define SMEM_BYTES     (2 * BUF_BYTES)                 // 128 KB

__device__ __forceinline__ void bulk_store(float* gdst, uint32_t s_src, uint32_t nbytes) {
    asm volatile(
        "cp.async.bulk.global.shared::cta.bulk_group [%0], [%1], %2;"
        :: "l"(gdst), "r"(s_src), "r"(nbytes) : "memory");
}

__global__ __launch_bounds__(256) void context_embedding_kernel(
    const int*   __restrict__ token_ids,
    const float* __restrict__ context_features,  // [T,16]
    const float* __restrict__ special_table,     // [8,256]
    const float* __restrict__ cls_w,             // [3,256]
    const float* __restrict__ cls_b,
    const float* __restrict__ cls_ln_g,
    const float* __restrict__ cls_ln_b,
    const float* __restrict__ ctx_w,             // [16,256]
    const float* __restrict__ ctx_b,
    const float* __restrict__ ctx_ln_g,
    const float* __restrict__ ctx_ln_b,
    float*       __restrict__ out,               // [T,256]
    int T)
{
    extern __shared__ float smem[];              // 2 x 64 KB row buffers

    const int tid    = threadIdx.x;
    const int warpId = tid >> 5;
    const int lane   = tid & 31;

    const int ctaRow0 = blockIdx.x * ROWS_PER_CTA;
    if (ctaRow0 >= T) return;

    const float4 z = make_float4(0.f, 0.f, 0.f, 0.f);

    for (int c = 0; c < NUM_CHUNKS; c++) {
        const int buf = c & 1;
        float* __restrict__ bufBase = smem + buf * BUF_FLOATS;

        // Before reusing a buffer, wait until its previous bulk store has
        // finished reading SMEM (at most 1 younger group still unread).
        if (c >= 2) {
            if (tid == 0)
                asm volatile("cp.async.bulk.wait_group.read 1;" ::: "memory");
            __syncthreads();
        }

        // ── Fill 64 rows: each of 8 warps builds 8 consecutive rows. ──
        const int rowBase = ctaRow0 + c * CHUNK_ROWS;     // global row of chunk
        const int wRow0   = rowBase + warpId * 8;          // this warp's rows

        int myTok = 0;
        if (lane < 8) myTok = token_ids[wRow0 + lane];
        const bool isSpec = (lane < 8) &&
            (myTok >= SPECIAL_OFFSET) && (myTok < SPECIAL_OFFSET + NUM_SPECIAL);
        const unsigned specMask = __ballot_sync(FULL, isSpec);
        const unsigned lnMask   = __ballot_sync(FULL, isSpec && (myTok <= SPECIAL_OFFSET + 1));

        // Lane l owns floats [4l,4l+4) and [128+4l,128+4l+4) of each row
        // -> STS.128 at addresses l*16: fully conflict-free.
        float4* __restrict__ row4 =
            reinterpret_cast<float4*>(bufBase + (warpId * 8) * ROW_FLOATS);

        #pragma unroll
        for (int t = 0; t < 8; t++, row4 += ROW_FLOATS / 4) {
            if (!((specMask >> t) & 1u)) {
                row4[lane]      = z;
                row4[32 + lane] = z;
                continue;
            }

            const int tok = __shfl_sync(FULL, myTok, t);
            const int sid = tok - SPECIAL_OFFSET;

            const float4* __restrict__ sp4 =
                reinterpret_cast<const float4*>(special_table + sid * D_MODEL);
            float4 e0 = sp4[lane];
            float4 e1 = sp4[32 + lane];

            if ((lnMask >> t) & 1u) {
                // Rare (~2.6%): Linear -> LayerNorm -> ReLU, added on top.
                const bool is_cls = (sid == 0);
                const int K = is_cls ? 3 : NUM_CONTEXT;
                const float* __restrict__ w  = is_cls ? cls_w    : ctx_w;
                const float* __restrict__ bi = is_cls ? cls_b    : ctx_b;
                const float* __restrict__ g  = is_cls ? cls_ln_g : ctx_ln_g;
                const float* __restrict__ bb = is_cls ? cls_ln_b : ctx_ln_b;

                const float* __restrict__ f =
                    context_features + (size_t)(wRow0 + t) * NUM_CONTEXT;

                const float4* bi4 = reinterpret_cast<const float4*>(bi);
                const float4 a0 = bi4[lane];
                const float4 a1 = bi4[32 + lane];
                float h[8] = {a0.x, a0.y, a0.z, a0.w, a1.x, a1.y, a1.z, a1.w};

                for (int k = 0; k < K; k++) {
                    const float fk = f[k];           // uniform -> broadcast
                    const float4* w4 = reinterpret_cast<const float4*>(w + k * D_MODEL);
                    const float4 w0 = w4[lane];
                    const float4 w1 = w4[32 + lane];
                    h[0] = fmaf(fk, w0.x, h[0]); h[1] = fmaf(fk, w0.y, h[1]);
                    h[2] = fmaf(fk, w0.z, h[2]); h[3] = fmaf(fk, w0.w, h[3]);
                    h[4] = fmaf(fk, w1.x, h[4]); h[5] = fmaf(fk, w1.y, h[5]);
                    h[6] = fmaf(fk, w1.z, h[6]); h[7] = fmaf(fk, w1.w, h[7]);
                }

                float s = 0.f, s2 = 0.f;
                #pragma unroll
                for (int j = 0; j < 8; j++) { s += h[j]; s2 += h[j] * h[j]; }
                #pragma unroll
                for (int off = 16; off > 0; off >>= 1) {
                    s  += __shfl_xor_sync(FULL, s,  off);
                    s2 += __shfl_xor_sync(FULL, s2, off);
                }
                const float mu   = s * (1.0f / D_MODEL);
                const float var  = fmaxf(s2 * (1.0f / D_MODEL) - mu * mu, 0.f);
                const float rstd = rsqrtf(var + LN_EPS);

                const float4* g4  = reinterpret_cast<const float4*>(g);
                const float4* bb4 = reinterpret_cast<const float4*>(bb);
                const float4 g0 = g4[lane],  g1 = g4[32 + lane];
                const float4 b0 = bb4[lane], b1 = bb4[32 + lane];

                e0.x += fmaxf((h[0] - mu) * rstd * g0.x + b0.x, 0.f);
                e0.y += fmaxf((h[1] - mu) * rstd * g0.y + b0.y, 0.f);
                e0.z += fmaxf((h[2] - mu) * rstd * g0.z + b0.z, 0.f);
                e0.w += fmaxf((h[3] - mu) * rstd * g0.w + b0.w, 0.f);
                e1.x += fmaxf((h[4] - mu) * rstd * g1.x + b1.x, 0.f);
                e1.y += fmaxf((h[5] - mu) * rstd * g1.y + b1.y, 0.f);
                e1.z += fmaxf((h[6] - mu) * rstd * g1.z + b1.z, 0.f);
                e1.w += fmaxf((h[7] - mu) * rstd * g1.w + b1.w, 0.f);
            }

            row4[lane]      = e0;
            row4[32 + lane] = e1;
        }

        __syncthreads();  // chunk fully built in SMEM

        if (tid == 0) {
            // Order generic-proxy STS before the async-proxy bulk read.
            asm volatile("fence.proxy.async.shared::cta;" ::: "memory");
            uint32_t s_src = (uint32_t)__cvta_generic_to_shared(bufBase);
            bulk_store(out + (size_t)rowBase * ROW_FLOATS, s_src, BUF_BYTES);
            asm volatile("cp.async.bulk.commit_group;" ::: "memory");
        }
    }

    // Drain all pending bulk stores before kernel exit.
    if (tid == 0)
        asm volatile("cp.async.bulk.wait_group 0;" ::: "memory");
}

extern "C" void kernel_launch(void* const* d_in, const int* in_sizes, int n_in,
                              void* d_out, int out_size)
{
    const int*   token_ids        = (const int*)  d_in[0];
    const float* context_features = (const float*)d_in[1];
    const float* special_table    = (const float*)d_in[2];
    const float* cls_w            = (const float*)d_in[3];
    const float* cls_b            = (const float*)d_in[4];
    const float* cls_ln_g         = (const float*)d_in[5];
    const float* cls_ln_b         = (const float*)d_in[6];
    const float* ctx_w            = (const float*)d_in[7];
    const float* ctx_b            = (const float*)d_in[8];
    const float* ctx_ln_g         = (const float*)d_in[9];
    const float* ctx_ln_b         = (const float*)d_in[10];
    float* out = (float*)d_out;

    const int T = in_sizes[0];                               // 131072
    const int blocks = (T + ROWS_PER_CTA - 1) / ROWS_PER_CTA; // 512

    cudaFuncSetAttribute(context_embedding_kernel,
                         cudaFuncAttributeMaxDynamicSharedMemorySize, SMEM_BYTES);

    context_embedding_kernel<<<blocks, 256, SMEM_BYTES>>>(
        token_ids, context_features, special_table,
        cls_w, cls_b, cls_ln_g, cls_ln_b,
        ctx_w, ctx_b, ctx_ln_g, ctx_ln_b,
        out, T);
}

// round 12
// speedup vs baseline: 1.4494x; 1.4494x over previous
#include <cuda_runtime.h>
#include <cstdint>

// ContextEmbedding: B=256, S=512, D=256. token ids in [0,76); special=[68,76);
// CLS=68, CONTEXT=69. Output f32 [B*S,256] = 134 MB.
//
// R12 (= R10 design, third submission after two infra-level container
// failures): pipelined TMA bulk-store drain.
//  - 512 CTAs x 256 rows; SMEM = 4 stages x 16 KB (64 KB) -> 3 CTAs/SM.
//  - All 256 token ids preloaded to registers BEFORE the chunk loop; chunk
//    fill is pure conflict-free STS (no global-load dependency).
//  - 16 chunks/CTA, ring of 4 stages, wait_group.read 3 -> up to 3 bulk
//    stores in flight per CTA (~9/SM) to cover L2 write latency.

#define D_MODEL        256
#define NUM_CONTEXT    16
#define SPECIAL_OFFSET 68
#define NUM_SPECIAL    8
#define LN_EPS         1e-5f
#define FULL           0xffffffffu

#define ROWS_PER_CTA   256
#define CHUNK_ROWS     16
#define NUM_CHUNKS     (ROWS_PER_CTA / CHUNK_ROWS)   // 16
#define STAGES         4
#define BUF_FLOATS     (CHUNK_ROWS * D_MODEL)        // 4096 floats = 16 KB
#define BUF_BYTES      (BUF_FLOATS * 4)              // 16384
#define SMEM_BYTES     (STAGES * BUF_BYTES)          // 64 KB

__device__ __forceinline__ void bulk_store(float* gdst, uint32_t s_src, uint32_t nbytes) {
    asm volatile(
        "cp.async.bulk.global.shared::cta.bulk_group [%0], [%1], %2;"
        :: "l"(gdst), "r"(s_src), "r"(nbytes) : "memory");
}

__global__ __launch_bounds__(256) void context_embedding_kernel(
    const int*   __restrict__ token_ids,
    const float* __restrict__ context_features,  // [T,16]
    const float* __restrict__ special_table,     // [8,256]
    const float* __restrict__ cls_w,             // [3,256]
    const float* __restrict__ cls_b,
    const float* __restrict__ cls_ln_g,
    const float* __restrict__ cls_ln_b,
    const float* __restrict__ ctx_w,             // [16,256]
    const float* __restrict__ ctx_b,
    const float* __restrict__ ctx_ln_g,
    const float* __restrict__ ctx_ln_b,
    float*       __restrict__ out,               // [T,256]
    int T)
{
    extern __shared__ float smem[];              // 4 x 16 KB stage buffers

    const int tid    = threadIdx.x;
    const int warpId = tid >> 5;                 // 0..7
    const int lane   = tid & 31;

    const int ctaRow0 = blockIdx.x * ROWS_PER_CTA;
    if (ctaRow0 >= T) return;

    // ── Preload ALL 256 ids for this CTA. Warp w owns rows {2w, 2w+1} of
    //    every chunk; lane l holds the id of rowInCta = (l>>1)*16 + 2w + (l&1),
    //    i.e. chunk c's two rows live in lanes 2c and 2c+1. ──
    const int myRowInCta = ((lane >> 1) * CHUNK_ROWS) + 2 * warpId + (lane & 1);
    const int myTok = token_ids[ctaRow0 + myRowInCta];

    const bool isSpec = (myTok >= SPECIAL_OFFSET) && (myTok < SPECIAL_OFFSET + NUM_SPECIAL);
    const unsigned specMask = __ballot_sync(FULL, isSpec);
    const unsigned lnMask   = __ballot_sync(FULL, isSpec && (myTok <= SPECIAL_OFFSET + 1));

    const float4 z = make_float4(0.f, 0.f, 0.f, 0.f);

    for (int c = 0; c < NUM_CHUNKS; c++) {
        float* __restrict__ buf = smem + (c & (STAGES - 1)) * BUF_FLOATS;

        // Ring backpressure: buffer (c mod 4) was drained by group c-4.
        if (c >= STAGES) {
            if (tid == 0)
                asm volatile("cp.async.bulk.wait_group.read %0;" :: "n"(STAGES - 1) : "memory");
        }
        __syncthreads();

        // ── Fill: warp w builds rows 2w and 2w+1 of this 16-row chunk. ──
        #pragma unroll
        for (int j = 0; j < 2; j++) {
            const int srcLane  = 2 * c + j;
            const int rowInCta = c * CHUNK_ROWS + 2 * warpId + j;

            float4* __restrict__ row4 =
                reinterpret_cast<float4*>(buf + (2 * warpId + j) * D_MODEL);

            if (!((specMask >> srcLane) & 1u)) {
                row4[lane]      = z;
                row4[32 + lane] = z;
                continue;
            }

            const int tok = __shfl_sync(FULL, myTok, srcLane);
            const int sid = tok - SPECIAL_OFFSET;

            const float4* __restrict__ sp4 =
                reinterpret_cast<const float4*>(special_table + sid * D_MODEL);
            float4 e0 = sp4[lane];
            float4 e1 = sp4[32 + lane];

            if ((lnMask >> srcLane) & 1u) {
                // Rare (~2.6%): Linear -> LayerNorm -> ReLU, added on top.
                const bool is_cls = (sid == 0);
                const int K = is_cls ? 3 : NUM_CONTEXT;
                const float* __restrict__ w  = is_cls ? cls_w    : ctx_w;
                const float* __restrict__ bi = is_cls ? cls_b    : ctx_b;
                const float* __restrict__ g  = is_cls ? cls_ln_g : ctx_ln_g;
                const float* __restrict__ bb = is_cls ? cls_ln_b : ctx_ln_b;

                const float* __restrict__ f =
                    context_features + (size_t)(ctaRow0 + rowInCta) * NUM_CONTEXT;

                const float4* bi4 = reinterpret_cast<const float4*>(bi);
                const float4 a0 = bi4[lane];
                const float4 a1 = bi4[32 + lane];
                float h[8] = {a0.x, a0.y, a0.z, a0.w, a1.x, a1.y, a1.z, a1.w};

                for (int k = 0; k < K; k++) {
                    const float fk = f[k];           // uniform -> broadcast
                    const float4* w4 = reinterpret_cast<const float4*>(w + k * D_MODEL);
                    const float4 w0 = w4[lane];
                    const float4 w1 = w4[32 + lane];
                    h[0] = fmaf(fk, w0.x, h[0]); h[1] = fmaf(fk, w0.y, h[1]);
                    h[2] = fmaf(fk, w0.z, h[2]); h[3] = fmaf(fk, w0.w, h[3]);
                    h[4] = fmaf(fk, w1.x, h[4]); h[5] = fmaf(fk, w1.y, h[5]);
                    h[6] = fmaf(fk, w1.z, h[6]); h[7] = fmaf(fk, w1.w, h[7]);
                }

                float s = 0.f, s2 = 0.f;
                #pragma unroll
                for (int i = 0; i < 8; i++) { s += h[i]; s2 += h[i] * h[i]; }
                #pragma unroll
                for (int off = 16; off > 0; off >>= 1) {
                    s  += __shfl_xor_sync(FULL, s,  off);
                    s2 += __shfl_xor_sync(FULL, s2, off);
                }
                const float mu   = s * (1.0f / D_MODEL);
                const float var  = fmaxf(s2 * (1.0f / D_MODEL) - mu * mu, 0.f);
                const float rstd = rsqrtf(var + LN_EPS);

                const float4* g4  = reinterpret_cast<const float4*>(g);
                const float4* bb4 = reinterpret_cast<const float4*>(bb);
                const float4 g0 = g4[lane],  g1 = g4[32 + lane];
                const float4 b0 = bb4[lane], b1 = bb4[32 + lane];

                e0.x += fmaxf((h[0] - mu) * rstd * g0.x + b0.x, 0.f);
                e0.y += fmaxf((h[1] - mu) * rstd * g0.y + b0.y, 0.f);
                e0.z += fmaxf((h[2] - mu) * rstd * g0.z + b0.z, 0.f);
                e0.w += fmaxf((h[3] - mu) * rstd * g0.w + b0.w, 0.f);
                e1.x += fmaxf((h[4] - mu) * rstd * g1.x + b1.x, 0.f);
                e1.y += fmaxf((h[5] - mu) * rstd * g1.y + b1.y, 0.f);
                e1.z += fmaxf((h[6] - mu) * rstd * g1.z + b1.z, 0.f);
                e1.w += fmaxf((h[7] - mu) * rstd * g1.w + b1.w, 0.f);
            }

            row4[lane]      = e0;
            row4[32 + lane] = e1;
        }

        // Make generic-proxy STS visible to the async proxy, then sync.
        asm volatile("fence.proxy.async.shared::cta;" ::: "memory");
        __syncthreads();

        if (tid == 0) {
            uint32_t s_src = (uint32_t)__cvta_generic_to_shared(buf);
            bulk_store(out + (size_t)(ctaRow0 + c * CHUNK_ROWS) * D_MODEL,
                       s_src, BUF_BYTES);
            asm volatile("cp.async.bulk.commit_group;" ::: "memory");
        }
    }

    // Drain all pending bulk stores before exit.
    if (tid == 0)
        asm volatile("cp.async.bulk.wait_group 0;" ::: "memory");
}

extern "C" void kernel_launch(void* const* d_in, const int* in_sizes, int n_in,
                              void* d_out, int out_size)
{
    const int*   token_ids        = (const int*)  d_in[0];
    const float* context_features = (const float*)d_in[1];
    const float* special_table    = (const float*)d_in[2];
    const float* cls_w            = (const float*)d_in[3];
    const float* cls_b            = (const float*)d_in[4];
    const float* cls_ln_g         = (const float*)d_in[5];
    const float* cls_ln_b         = (const float*)d_in[6];
    const float* ctx_w            = (const float*)d_in[7];
    const float* ctx_b            = (const float*)d_in[8];
    const float* ctx_ln_g         = (const float*)d_in[9];
    const float* ctx_ln_b         = (const float*)d_in[10];
    float* out = (float*)d_out;

    const int T = in_sizes[0];                                // 131072
    const int blocks = (T + ROWS_PER_CTA - 1) / ROWS_PER_CTA; // 512

    cudaFuncSetAttribute(context_embedding_kernel,
                         cudaFuncAttributeMaxDynamicSharedMemorySize, SMEM_BYTES);

    context_embedding_kernel<<<blocks, 256, SMEM_BYTES>>>(
        token_ids, context_features, special_table,
        cls_w, cls_b, cls_ln_g, cls_ln_b,
        ctx_w, ctx_b, ctx_ln_g, ctx_ln_b,
        out, T);
}

// round 13
// speedup vs baseline: 1.5131x; 1.0440x over previous
#include <cuda_runtime.h>
#include <cstdint>

// ContextEmbedding: B=256, S=512, D=256. token ids in [0,76); special=[68,76);
// CLS=68, CONTEXT=69. Output f32 [B*S,256] = 134 MB.
//
// R13: DUAL-PATH store. STG path plateaus at ~5.1 TB/s (R2-R7), TMA bulk path
// delivers ~3.6 TB/s (R12) — different SM-side machinery, converging only at
// L2 (which has ~2x headroom). Run both concurrently on disjoint rows:
//   - CTAs with bid%32 < 19 (59%): R2-style per-thread STG (warp = 32 rows).
//   - CTAs with bid%32 >= 19 (41%): R12-style SMEM-staged TMA bulk drain
//     (4-stage ring, 16-row/16KB chunks, ids preloaded).
// Interleaved bids put both CTA types on every SM.

#define D_MODEL        256
#define NUM_CONTEXT    16
#define SPECIAL_OFFSET 68
#define NUM_SPECIAL    8
#define LN_EPS         1e-5f
#define FULL           0xffffffffu

#define ROWS_PER_CTA   256
#define CHUNK_ROWS     16
#define NUM_CHUNKS     (ROWS_PER_CTA / CHUNK_ROWS)   // 16
#define STAGES         4
#define BUF_FLOATS     (CHUNK_ROWS * D_MODEL)        // 16 KB
#define BUF_BYTES      (BUF_FLOATS * 4)
#define SMEM_BYTES     (STAGES * BUF_BYTES)          // 64 KB
#define STG_CTAS_MOD   19                            // of 32: ~59% STG

__device__ __forceinline__ void bulk_store(float* gdst, uint32_t s_src, uint32_t nbytes) {
    asm volatile(
        "cp.async.bulk.global.shared::cta.bulk_group [%0], [%1], %2;"
        :: "l"(gdst), "r"(s_src), "r"(nbytes) : "memory");
}

// Build one special row's value (warp-collective; lane owns float4 pairs
// [4*lane,4*lane+4) and [128+4*lane, ...+4)). doLn => CLS/CONTEXT branch.
__device__ __forceinline__ void build_special_row(
    int sid, bool doLn, int globalRow, int lane,
    const float* __restrict__ special_table,
    const float* __restrict__ context_features,
    const float* __restrict__ cls_w, const float* __restrict__ cls_b,
    const float* __restrict__ cls_ln_g, const float* __restrict__ cls_ln_b,
    const float* __restrict__ ctx_w, const float* __restrict__ ctx_b,
    const float* __restrict__ ctx_ln_g, const float* __restrict__ ctx_ln_b,
    float4& e0, float4& e1)
{
    const float4* __restrict__ sp4 =
        reinterpret_cast<const float4*>(special_table + sid * D_MODEL);
    e0 = sp4[lane];
    e1 = sp4[32 + lane];

    if (!doLn) return;

    const bool is_cls = (sid == 0);
    const int K = is_cls ? 3 : NUM_CONTEXT;
    const float* __restrict__ w  = is_cls ? cls_w    : ctx_w;
    const float* __restrict__ bi = is_cls ? cls_b    : ctx_b;
    const float* __restrict__ g  = is_cls ? cls_ln_g : ctx_ln_g;
    const float* __restrict__ bb = is_cls ? cls_ln_b : ctx_ln_b;

    const float* __restrict__ f = context_features + (size_t)globalRow * NUM_CONTEXT;

    const float4* bi4 = reinterpret_cast<const float4*>(bi);
    const float4 a0 = bi4[lane];
    const float4 a1 = bi4[32 + lane];
    float h[8] = {a0.x, a0.y, a0.z, a0.w, a1.x, a1.y, a1.z, a1.w};

    for (int k = 0; k < K; k++) {
        const float fk = f[k];  // uniform address -> broadcast
        const float4* w4 = reinterpret_cast<const float4*>(w + k * D_MODEL);
        const float4 w0 = w4[lane];
        const float4 w1 = w4[32 + lane];
        h[0] = fmaf(fk, w0.x, h[0]); h[1] = fmaf(fk, w0.y, h[1]);
        h[2] = fmaf(fk, w0.z, h[2]); h[3] = fmaf(fk, w0.w, h[3]);
        h[4] = fmaf(fk, w1.x, h[4]); h[5] = fmaf(fk, w1.y, h[5]);
        h[6] = fmaf(fk, w1.z, h[6]); h[7] = fmaf(fk, w1.w, h[7]);
    }

    float s = 0.f, s2 = 0.f;
    #pragma unroll
    for (int i = 0; i < 8; i++) { s += h[i]; s2 += h[i] * h[i]; }
    #pragma unroll
    for (int off = 16; off > 0; off >>= 1) {
        s  += __shfl_xor_sync(FULL, s,  off);
        s2 += __shfl_xor_sync(FULL, s2, off);
    }
    const float mu   = s * (1.0f / D_MODEL);
    const float var  = fmaxf(s2 * (1.0f / D_MODEL) - mu * mu, 0.f);
    const float rstd = rsqrtf(var + LN_EPS);

    const float4* g4  = reinterpret_cast<const float4*>(g);
    const float4* bb4 = reinterpret_cast<const float4*>(bb);
    const float4 g0 = g4[lane],  g1 = g4[32 + lane];
    const float4 b0 = bb4[lane], b1 = bb4[32 + lane];

    e0.x += fmaxf((h[0] - mu) * rstd * g0.x + b0.x, 0.f);
    e0.y += fmaxf((h[1] - mu) * rstd * g0.y + b0.y, 0.f);
    e0.z += fmaxf((h[2] - mu) * rstd * g0.z + b0.z, 0.f);
    e0.w += fmaxf((h[3] - mu) * rstd * g0.w + b0.w, 0.f);
    e1.x += fmaxf((h[4] - mu) * rstd * g1.x + b1.x, 0.f);
    e1.y += fmaxf((h[5] - mu) * rstd * g1.y + b1.y, 0.f);
    e1.z += fmaxf((h[6] - mu) * rstd * g1.z + b1.z, 0.f);
    e1.w += fmaxf((h[7] - mu) * rstd * g1.w + b1.w, 0.f);
}

__global__ __launch_bounds__(256) void context_embedding_kernel(
    const int*   __restrict__ token_ids,
    const float* __restrict__ context_features,
    const float* __restrict__ special_table,
    const float* __restrict__ cls_w, const float* __restrict__ cls_b,
    const float* __restrict__ cls_ln_g, const float* __restrict__ cls_ln_b,
    const float* __restrict__ ctx_w, const float* __restrict__ ctx_b,
    const float* __restrict__ ctx_ln_g, const float* __restrict__ ctx_ln_b,
    float*       __restrict__ out,
    int T)
{
    extern __shared__ float smem[];

    const int tid    = threadIdx.x;
    const int warpId = tid >> 5;
    const int lane   = tid & 31;

    const int ctaRow0 = blockIdx.x * ROWS_PER_CTA;
    if (ctaRow0 >= T) return;

    const float4 z = make_float4(0.f, 0.f, 0.f, 0.f);

    if ((blockIdx.x & 31) < STG_CTAS_MOD) {
        // ───────────────── STG path (R2): warp owns 32 consecutive rows ──
        const int tokBase = ctaRow0 + warpId * 32;
        const int myTok = token_ids[tokBase + lane];

        const bool isSpec = (myTok >= SPECIAL_OFFSET) &&
                            (myTok < SPECIAL_OFFSET + NUM_SPECIAL);
        const unsigned specMask = __ballot_sync(FULL, isSpec);
        const unsigned lnMask   = __ballot_sync(FULL, isSpec && (myTok <= SPECIAL_OFFSET + 1));

        float4* __restrict__ row4 =
            reinterpret_cast<float4*>(out + (size_t)tokBase * D_MODEL);

        #pragma unroll 4
        for (int t = 0; t < 32; t++, row4 += D_MODEL / 4) {
            if (!((specMask >> t) & 1u)) {
                row4[lane]      = z;
                row4[32 + lane] = z;
                continue;
            }
            const int tok = __shfl_sync(FULL, myTok, t);
            float4 e0, e1;
            build_special_row(tok - SPECIAL_OFFSET, (lnMask >> t) & 1u,
                              tokBase + t, lane,
                              special_table, context_features,
                              cls_w, cls_b, cls_ln_g, cls_ln_b,
                              ctx_w, ctx_b, ctx_ln_g, ctx_ln_b, e0, e1);
            row4[lane]      = e0;
            row4[32 + lane] = e1;
        }
    } else {
        // ───────────────── TMA path (R12): SMEM stage + bulk drain ──────
        // Lane l holds id of rowInCta = (l>>1)*16 + 2w + (l&1):
        // chunk c's two rows for warp w live in lanes 2c, 2c+1.
        const int myRowInCta = ((lane >> 1) * CHUNK_ROWS) + 2 * warpId + (lane & 1);
        const int myTok = token_ids[ctaRow0 + myRowInCta];

        const bool isSpec = (myTok >= SPECIAL_OFFSET) &&
                            (myTok < SPECIAL_OFFSET + NUM_SPECIAL);
        const unsigned specMask = __ballot_sync(FULL, isSpec);
        const unsigned lnMask   = __ballot_sync(FULL, isSpec && (myTok <= SPECIAL_OFFSET + 1));

        for (int c = 0; c < NUM_CHUNKS; c++) {
            float* __restrict__ buf = smem + (c & (STAGES - 1)) * BUF_FLOATS;

            if (c >= STAGES) {
                if (tid == 0)
                    asm volatile("cp.async.bulk.wait_group.read %0;"
                                 :: "n"(STAGES - 1) : "memory");
            }
            __syncthreads();

            #pragma unroll
            for (int j = 0; j < 2; j++) {
                const int srcLane  = 2 * c + j;
                const int rowInCta = c * CHUNK_ROWS + 2 * warpId + j;

                float4* __restrict__ row4 =
                    reinterpret_cast<float4*>(buf + (2 * warpId + j) * D_MODEL);

                if (!((specMask >> srcLane) & 1u)) {
                    row4[lane]      = z;
                    row4[32 + lane] = z;
                    continue;
                }
                const int tok = __shfl_sync(FULL, myTok, srcLane);
                float4 e0, e1;
                build_special_row(tok - SPECIAL_OFFSET, (lnMask >> srcLane) & 1u,
                                  ctaRow0 + rowInCta, lane,
                                  special_table, context_features,
                                  cls_w, cls_b, cls_ln_g, cls_ln_b,
                                  ctx_w, ctx_b, ctx_ln_g, ctx_ln_b, e0, e1);
                row4[lane]      = e0;
                row4[32 + lane] = e1;
            }

            asm volatile("fence.proxy.async.shared::cta;" ::: "memory");
            __syncthreads();

            if (tid == 0) {
                uint32_t s_src = (uint32_t)__cvta_generic_to_shared(buf);
                bulk_store(out + (size_t)(ctaRow0 + c * CHUNK_ROWS) * D_MODEL,
                           s_src, BUF_BYTES);
                asm volatile("cp.async.bulk.commit_group;" ::: "memory");
            }
        }

        if (tid == 0)
            asm volatile("cp.async.bulk.wait_group 0;" ::: "memory");
    }
}

extern "C" void kernel_launch(void* const* d_in, const int* in_sizes, int n_in,
                              void* d_out, int out_size)
{
    const int*   token_ids        = (const int*)  d_in[0];
    const float* context_features = (const float*)d_in[1];
    const float* special_table    = (const float*)d_in[2];
    const float* cls_w            = (const float*)d_in[3];
    const float* cls_b            = (const float*)d_in[4];
    const float* cls_ln_g         = (const float*)d_in[5];
    const float* cls_ln_b         = (const float*)d_in[6];
    const float* ctx_w            = (const float*)d_in[7];
    const float* ctx_b            = (const float*)d_in[8];
    const float* ctx_ln_g         = (const float*)d_in[9];
    const float* ctx_ln_b         = (const float*)d_in[10];
    float* out = (float*)d_out;

    const int T = in_sizes[0];                                // 131072
    const int blocks = (T + ROWS_PER_CTA - 1) / ROWS_PER_CTA; // 512

    cudaFuncSetAttribute(context_embedding_kernel,
                         cudaFuncAttributeMaxDynamicSharedMemorySize, SMEM_BYTES);

    context_embedding_kernel<<<blocks, 256, SMEM_BYTES>>>(
        token_ids, context_features, special_table,
        cls_w, cls_b, cls_ln_g, cls_ln_b,
        ctx_w, ctx_b, ctx_ln_g, ctx_ln_b,
        out, T);
}

// round 14
// speedup vs baseline: 1.8646x; 1.2323x over previous
#include <cuda_runtime.h>

// ContextEmbedding: B=256, S=512, D=256. token ids in [0,76); special = [68,76);
// CLS=68, CONTEXT=69. Output f32 [B*S, 256] = 134 MB -> pure store-bound.
//
// R14 (final): the R2 winner. Eight rounds established ~5.1 TB/s as the
// machine plateau for this write stream (invariant across store width,
// cache policy, occupancy, and STG-vs-TMA engine). Config: 32 tokens/warp,
// 512 blocks, streaming float4 stores, unroll 8 for deeper store ILP.

#define D_MODEL        256
#define NUM_CONTEXT    16
#define SPECIAL_OFFSET 68
#define NUM_SPECIAL    8
#define LN_EPS         1e-5f
#define FULL           0xffffffffu
#define TOK_PER_WARP   32

__global__ __launch_bounds__(256) void context_embedding_kernel(
    const int*   __restrict__ token_ids,
    const float* __restrict__ context_features,  // [T,16]
    const float* __restrict__ special_table,     // [8,256]
    const float* __restrict__ cls_w,             // [3,256]
    const float* __restrict__ cls_b,
    const float* __restrict__ cls_ln_g,
    const float* __restrict__ cls_ln_b,
    const float* __restrict__ ctx_w,             // [16,256]
    const float* __restrict__ ctx_b,
    const float* __restrict__ ctx_ln_g,
    const float* __restrict__ ctx_ln_b,
    float*       __restrict__ out,               // [T,256]
    int T)
{
    const int warpId  = threadIdx.x >> 5;
    const int lane    = threadIdx.x & 31;
    const int tokBase = (blockIdx.x * 8 + warpId) * TOK_PER_WARP;
    if (tokBase >= T) return;

    // One coalesced 128B load of this warp's 32 token ids.
    const int myTok = token_ids[tokBase + lane];

    const bool isSpec = (myTok >= SPECIAL_OFFSET) && (myTok < SPECIAL_OFFSET + NUM_SPECIAL);
    const unsigned specMask = __ballot_sync(FULL, isSpec);
    const unsigned lnMask   = __ballot_sync(FULL, isSpec && (myTok <= SPECIAL_OFFSET + 1));

    const float4 z = make_float4(0.f, 0.f, 0.f, 0.f);

    // Lane l owns float4 chunks [4l,4l+4) and [128+4l,128+4l+4) of each row.
    float4* __restrict__ row4 =
        reinterpret_cast<float4*>(out + (size_t)tokBase * D_MODEL);

    #pragma unroll 8
    for (int t = 0; t < TOK_PER_WARP; t++, row4 += D_MODEL / 4) {
        if (!((specMask >> t) & 1u)) {
            // Zero row (89.5%): two independent streaming STG.128 per lane.
            __stcs(&row4[lane],      z);
            __stcs(&row4[32 + lane], z);
            continue;
        }

        const int tok = __shfl_sync(FULL, myTok, t);
        const int sid = tok - SPECIAL_OFFSET;

        const float4* __restrict__ sp4 =
            reinterpret_cast<const float4*>(special_table + sid * D_MODEL);
        float4 e0 = sp4[lane];
        float4 e1 = sp4[32 + lane];

        if ((lnMask >> t) & 1u) {
            // Rare branch (~2.6%): Linear -> LayerNorm -> ReLU, added on top.
            const bool is_cls = (sid == 0);
            const int K = is_cls ? 3 : NUM_CONTEXT;
            const float* __restrict__ w  = is_cls ? cls_w    : ctx_w;
            const float* __restrict__ bi = is_cls ? cls_b    : ctx_b;
            const float* __restrict__ g  = is_cls ? cls_ln_g : ctx_ln_g;
            const float* __restrict__ bb = is_cls ? cls_ln_b : ctx_ln_b;

            const float* __restrict__ f =
                context_features + (size_t)(tokBase + t) * NUM_CONTEXT;

            const float4* bi4 = reinterpret_cast<const float4*>(bi);
            const float4 a0 = bi4[lane];
            const float4 a1 = bi4[32 + lane];
            float h[8] = {a0.x, a0.y, a0.z, a0.w, a1.x, a1.y, a1.z, a1.w};

            for (int k = 0; k < K; k++) {
                const float fk = f[k];  // uniform address -> broadcast
                const float4* w4 = reinterpret_cast<const float4*>(w + k * D_MODEL);
                const float4 w0 = w4[lane];
                const float4 w1 = w4[32 + lane];
                h[0] = fmaf(fk, w0.x, h[0]); h[1] = fmaf(fk, w0.y, h[1]);
                h[2] = fmaf(fk, w0.z, h[2]); h[3] = fmaf(fk, w0.w, h[3]);
                h[4] = fmaf(fk, w1.x, h[4]); h[5] = fmaf(fk, w1.y, h[5]);
                h[6] = fmaf(fk, w1.z, h[6]); h[7] = fmaf(fk, w1.w, h[7]);
            }

            // LayerNorm over D=256: one-pass warp butterfly reduction.
            float s = 0.f, s2 = 0.f;
            #pragma unroll
            for (int i = 0; i < 8; i++) { s += h[i]; s2 += h[i] * h[i]; }
            #pragma unroll
            for (int off = 16; off > 0; off >>= 1) {
                s  += __shfl_xor_sync(FULL, s,  off);
                s2 += __shfl_xor_sync(FULL, s2, off);
            }
            const float mu   = s * (1.0f / D_MODEL);
            const float var  = fmaxf(s2 * (1.0f / D_MODEL) - mu * mu, 0.f);
            const float rstd = rsqrtf(var + LN_EPS);

            const float4* g4  = reinterpret_cast<const float4*>(g);
            const float4* bb4 = reinterpret_cast<const float4*>(bb);
            const float4 g0 = g4[lane],  g1 = g4[32 + lane];
            const float4 b0 = bb4[lane], b1 = bb4[32 + lane];

            e0.x += fmaxf((h[0] - mu) * rstd * g0.x + b0.x, 0.f);
            e0.y += fmaxf((h[1] - mu) * rstd * g0.y + b0.y, 0.f);
            e0.z += fmaxf((h[2] - mu) * rstd * g0.z + b0.z, 0.f);
            e0.w += fmaxf((h[3] - mu) * rstd * g0.w + b0.w, 0.f);
            e1.x += fmaxf((h[4] - mu) * rstd * g1.x + b1.x, 0.f);
            e1.y += fmaxf((h[5] - mu) * rstd * g1.y + b1.y, 0.f);
            e1.z += fmaxf((h[6] - mu) * rstd * g1.z + b1.z, 0.f);
            e1.w += fmaxf((h[7] - mu) * rstd * g1.w + b1.w, 0.f);
        }

        __stcs(&row4[lane],      e0);
        __stcs(&row4[32 + lane], e1);
    }
}

extern "C" void kernel_launch(void* const* d_in, const int* in_sizes, int n_in,
                              void* d_out, int out_size)
{
    const int*   token_ids        = (const int*)  d_in[0];
    const float* context_features = (const float*)d_in[1];
    const float* special_table    = (const float*)d_in[2];
    const float* cls_w            = (const float*)d_in[3];
    const float* cls_b            = (const float*)d_in[4];
    const float* cls_ln_g         = (const float*)d_in[5];
    const float* cls_ln_b         = (const float*)d_in[6];
    const float* ctx_w            = (const float*)d_in[7];
    const float* ctx_b            = (const float*)d_in[8];
    const float* ctx_ln_g         = (const float*)d_in[9];
    const float* ctx_ln_b         = (const float*)d_in[10];
    float* out = (float*)d_out;

    const int T = in_sizes[0];                         // B*S tokens = 131072
    const int tokens_per_block = 8 * TOK_PER_WARP;     // 256
    const int blocks = (T + tokens_per_block - 1) / tokens_per_block;  // 512

    context_embedding_kernel<<<blocks, 256>>>(
        token_ids, context_features, special_table,
        cls_w, cls_b, cls_ln_g, cls_ln_b,
        ctx_w, ctx_b, ctx_ln_g, ctx_ln_b,
        out, T);
}

// round 15
// speedup vs baseline: 1.8922x; 1.0148x over previous
#include <cuda_runtime.h>

// ContextEmbedding: B=256, S=512, D=256. token ids in [0,76); special = [68,76);
// CLS=68, CONTEXT=69. Output f32 [B*S, 256] = 134 MB -> pure store-bound.
//
// FINAL (= R2, session-best bench 29.888us): 32 tokens per warp, one coalesced
// 128B id load per warp, uniform loop with ballot/shfl broadcast. Zero rows
// (89.5%): 2 streaming STG.128 per lane. Special rows: 1KB L1-resident table
// gather. CLS/CONTEXT (~2.6%): tiny GEMV + warp-butterfly LayerNorm + ReLU.
// 512 blocks = single wave. Kernel is pinned at ~26-27us by the per-SM
// outstanding-store-credit ceiling (~5.1 TB/s write stream) — verified
// invariant across store width, cache policy, occupancy, and TMA engine.

#define D_MODEL        256
#define NUM_CONTEXT    16
#define SPECIAL_OFFSET 68
#define NUM_SPECIAL    8
#define LN_EPS         1e-5f
#define FULL           0xffffffffu
#define TOK_PER_WARP   32

__global__ __launch_bounds__(256) void context_embedding_kernel(
    const int*   __restrict__ token_ids,
    const float* __restrict__ context_features,  // [T,16]
    const float* __restrict__ special_table,     // [8,256]
    const float* __restrict__ cls_w,             // [3,256]
    const float* __restrict__ cls_b,
    const float* __restrict__ cls_ln_g,
    const float* __restrict__ cls_ln_b,
    const float* __restrict__ ctx_w,             // [16,256]
    const float* __restrict__ ctx_b,
    const float* __restrict__ ctx_ln_g,
    const float* __restrict__ ctx_ln_b,
    float*       __restrict__ out,               // [T,256]
    int T)
{
    const int warpId  = threadIdx.x >> 5;
    const int lane    = threadIdx.x & 31;
    const int tokBase = (blockIdx.x * 8 + warpId) * TOK_PER_WARP;
    if (tokBase >= T) return;

    // One coalesced load of this warp's 32 token ids.
    const int myTok = token_ids[tokBase + lane];

    // Bitmask of lanes whose token is special / needs the LN branch.
    const bool isSpec = (myTok >= SPECIAL_OFFSET) && (myTok < SPECIAL_OFFSET + NUM_SPECIAL);
    const unsigned specMask = __ballot_sync(FULL, isSpec);
    const unsigned lnMask   = __ballot_sync(FULL, isSpec && (myTok <= SPECIAL_OFFSET + 1));

    const float4 z = make_float4(0.f, 0.f, 0.f, 0.f);

    #pragma unroll 4
    for (int t = 0; t < TOK_PER_WARP; t++) {
        float4* __restrict__ out4 =
            reinterpret_cast<float4*>(out + (size_t)(tokBase + t) * D_MODEL);

        if (!((specMask >> t) & 1u)) {
            // Zero row: two independent streaming STG.128 per lane.
            __stcs(&out4[lane],      z);
            __stcs(&out4[32 + lane], z);
            continue;
        }

        const int tok = __shfl_sync(FULL, myTok, t);
        const int sid = tok - SPECIAL_OFFSET;

        const float4* __restrict__ sp4 =
            reinterpret_cast<const float4*>(special_table + sid * D_MODEL);
        float4 e0 = sp4[lane];
        float4 e1 = sp4[32 + lane];

        if ((lnMask >> t) & 1u) {
            const bool is_cls = (sid == 0);
            const int K = is_cls ? 3 : NUM_CONTEXT;
            const float* __restrict__ w  = is_cls ? cls_w    : ctx_w;
            const float* __restrict__ bi = is_cls ? cls_b    : ctx_b;
            const float* __restrict__ g  = is_cls ? cls_ln_g : ctx_ln_g;
            const float* __restrict__ bb = is_cls ? cls_ln_b : ctx_ln_b;

            const float* __restrict__ f =
                context_features + (size_t)(tokBase + t) * NUM_CONTEXT;

            const float4* bi4 = reinterpret_cast<const float4*>(bi);
            const float4 a0 = bi4[lane];
            const float4 a1 = bi4[32 + lane];
            float h[8] = {a0.x, a0.y, a0.z, a0.w, a1.x, a1.y, a1.z, a1.w};

            for (int k = 0; k < K; k++) {
                const float fk = f[k];  // uniform address -> broadcast
                const float4* w4 = reinterpret_cast<const float4*>(w + k * D_MODEL);
                const float4 w0 = w4[lane];
                const float4 w1 = w4[32 + lane];
                h[0] = fmaf(fk, w0.x, h[0]); h[1] = fmaf(fk, w0.y, h[1]);
                h[2] = fmaf(fk, w0.z, h[2]); h[3] = fmaf(fk, w0.w, h[3]);
                h[4] = fmaf(fk, w1.x, h[4]); h[5] = fmaf(fk, w1.y, h[5]);
                h[6] = fmaf(fk, w1.z, h[6]); h[7] = fmaf(fk, w1.w, h[7]);
            }

            // LayerNorm over D=256: one-pass warp butterfly reduction.
            float s = 0.f, s2 = 0.f;
            #pragma unroll
            for (int i = 0; i < 8; i++) { s += h[i]; s2 += h[i] * h[i]; }
            #pragma unroll
            for (int off = 16; off > 0; off >>= 1) {
                s  += __shfl_xor_sync(FULL, s,  off);
                s2 += __shfl_xor_sync(FULL, s2, off);
            }
            const float mu   = s * (1.0f / D_MODEL);
            const float var  = fmaxf(s2 * (1.0f / D_MODEL) - mu * mu, 0.f);
            const float rstd = rsqrtf(var + LN_EPS);

            const float4* g4  = reinterpret_cast<const float4*>(g);
            const float4* bb4 = reinterpret_cast<const float4*>(bb);
            const float4 g0 = g4[lane],  g1 = g4[32 + lane];
            const float4 b0 = bb4[lane], b1 = bb4[32 + lane];

            e0.x += fmaxf((h[0] - mu) * rstd * g0.x + b0.x, 0.f);
            e0.y += fmaxf((h[1] - mu) * rstd * g0.y + b0.y, 0.f);
            e0.z += fmaxf((h[2] - mu) * rstd * g0.z + b0.z, 0.f);
            e0.w += fmaxf((h[3] - mu) * rstd * g0.w + b0.w, 0.f);
            e1.x += fmaxf((h[4] - mu) * rstd * g1.x + b1.x, 0.f);
            e1.y += fmaxf((h[5] - mu) * rstd * g1.y + b1.y, 0.f);
            e1.z += fmaxf((h[6] - mu) * rstd * g1.z + b1.z, 0.f);
            e1.w += fmaxf((h[7] - mu) * rstd * g1.w + b1.w, 0.f);
        }

        __stcs(&out4[lane],      e0);
        __stcs(&out4[32 + lane], e1);
    }
}

extern "C" void kernel_launch(void* const* d_in, const int* in_sizes, int n_in,
                              void* d_out, int out_size)
{
    const int*   token_ids        = (const int*)  d_in[0];
    const float* context_features = (const float*)d_in[1];
    const float* special_table    = (const float*)d_in[2];
    const float* cls_w            = (const float*)d_in[3];
    const float* cls_b            = (const float*)d_in[4];
    const float* cls_ln_g         = (const float*)d_in[5];
    const float* cls_ln_b         = (const float*)d_in[6];
    const float* ctx_w            = (const float*)d_in[7];
    const float* ctx_b            = (const float*)d_in[8];
    const float* ctx_ln_g         = (const float*)d_in[9];
    const float* ctx_ln_b         = (const float*)d_in[10];
    float* out = (float*)d_out;

    const int T = in_sizes[0];                    // B*S tokens = 131072
    const int tokens_per_block = 8 * TOK_PER_WARP; // 256
    const int blocks = (T + tokens_per_block - 1) / tokens_per_block;  // 512

    context_embedding_kernel<<<blocks, 256>>>(
        token_ids, context_features, special_table,
        cls_w, cls_b, cls_ln_g, cls_ln_b,
        ctx_w, ctx_b, ctx_ln_g, ctx_ln_b,
        out, T);
}